// round 6
// baseline (speedup 1.0000x reference)
#include <cuda_runtime.h>
#include <cuda_bf16.h>
#include <mma.h>
#include <math.h>
#include <cstdint>

using namespace nvcuda;

#define BB 64
#define TT 512
#define HH 1024
#define BT (BB*TT)
#define NF 128
#define NCHUNK 64
#define ROWS_PER_CHUNK (BT/NCHUNK)  // 512
#define N3H (3*HH)                  // 3072
#define LDM 80                      // smem row stride (elems): 160B, 32B-aligned rows, 2-way ldsm conflicts only

// ---------------- device scratch (no allocations allowed) ----------------
__device__ float g_part_sum[NCHUNK][HH];
__device__ float g_part_sq[NCHUNK][HH];
__device__ float g_a[HH];
__device__ float g_C;
__device__ float g_WpL1;
__device__ unsigned g_pxmax_u;
__device__ float g_pxT[TT][BB];    // px transposed [t][b]
__device__ float g_phi[NF][HH];
__device__ float g_gi[NF][N3H];
__device__ float g_Ftab[NF];

__device__ __forceinline__ float domain_R() {
    float pxmax = __uint_as_float(g_pxmax_u);
    return 0.5f * (pxmax + g_WpL1) * 1.02f + 0.25f;
}

// ---------------- pass 1: per-channel BN partial sums ----------------
__global__ void k_stats(const float* __restrict__ x) {
    int ch = blockIdx.x * 256 + threadIdx.x;
    int r0 = blockIdx.y * ROWS_PER_CHUNK;
    const float* p = x + (size_t)r0 * HH + ch;
    float s = 0.f, q = 0.f;
#pragma unroll 16
    for (int r = 0; r < ROWS_PER_CHUNK; r++) {
        float v = p[(size_t)r * HH];
        s += v; q += v * v;
    }
    g_part_sum[blockIdx.y][ch] = s;
    g_part_sq[blockIdx.y][ch]  = q;
}

__global__ void k_finalize(const float* __restrict__ gamma, const float* __restrict__ beta,
                           const float* __restrict__ Wp, const float* __restrict__ bp) {
    int j = threadIdx.x;  // 1024
    float s = 0.f, q = 0.f;
#pragma unroll 8
    for (int c = 0; c < NCHUNK; c++) { s += g_part_sum[c][j]; q += g_part_sq[c][j]; }
    float mean = s * (1.0f / BT);
    float var  = q * (1.0f / BT) - mean * mean;
    float rstd = rsqrtf(var + 1e-5f);
    float gj = gamma[j], wj = Wp[j];
    g_a[j] = gj * rstd * wj;
    float cj = (beta[j] - mean * rstd * gj) * wj;
    float aw = fabsf(wj);
    __shared__ float sc[1024], sa[1024];
    sc[j] = cj; sa[j] = aw;
    __syncthreads();
    for (int st = 512; st > 0; st >>= 1) {
        if (j < st) { sc[j] += sc[j + st]; sa[j] += sa[j + st]; }
        __syncthreads();
    }
    if (j == 0) {
        g_C = sc[0] + bp[0];
        g_WpL1 = sa[0] + fabsf(bp[0]);
        g_pxmax_u = 0u;   // reset deterministic max for this replay
    }
}

// ---------------- pass 2: px -> transposed store + global max|px| ----------------
__global__ void k_px(const float* __restrict__ x) {
    int w = threadIdx.x >> 5, lane = threadIdx.x & 31;
    int r = blockIdx.x * 8 + w;
    const float4* xr = (const float4*)(x + (size_t)r * HH);
    const float4* a4 = (const float4*)g_a;
    float acc = 0.f;
#pragma unroll
    for (int i = 0; i < 8; i++) {
        float4 xv = xr[lane + i * 32];
        float4 av = __ldg(&a4[lane + i * 32]);
        acc += xv.x * av.x + xv.y * av.y + xv.z * av.z + xv.w * av.w;
    }
#pragma unroll
    for (int off = 16; off; off >>= 1) acc += __shfl_down_sync(0xFFFFFFFFu, acc, off);
    __shared__ float wm[8];
    if (lane == 0) {
        float v = acc + g_C;
        int b = r >> 9, t = r & (TT - 1);
        g_pxT[t][b] = v;
        wm[w] = fabsf(v);
    }
    __syncthreads();
    if (threadIdx.x == 0) {
        float m = wm[0];
#pragma unroll
        for (int i = 1; i < 8; i++) m = fmaxf(m, wm[i]);
        atomicMax(&g_pxmax_u, __float_as_uint(m));   // m >= 0: uint order == float order
    }
}

// ---------------- table build: layer-0 GRU-cell(h=0) at sample points ----------------
__global__ void k_phi(const float* __restrict__ W0, const float* __restrict__ bih0,
                      const float* __restrict__ bhh0) {
    float R = domain_R();
    float s0 = -R;
    float delta = 2.f * R / (float)(NF - 1);
    int i = blockIdx.x;
    int j = blockIdx.y * 256 + threadIdx.x;
    float s = s0 + (float)i * delta;
    float ar = fmaf(s, W0[j],          bih0[j]        + bhh0[j]);
    float az = fmaf(s, W0[HH + j],     bih0[HH + j]   + bhh0[HH + j]);
    float r = 1.f / (1.f + expf(-ar));
    float z = 1.f / (1.f + expf(-az));
    float an = fmaf(s, W0[2 * HH + j], fmaf(r, bhh0[2 * HH + j], bih0[2 * HH + j]));
    g_phi[i][j] = (1.f - z) * tanhf(an);
}

// ---------------- WMMA bf16 3-split GEMM: gi[128][3072] = phi @ W1^T ----------------
// grid (48, 2): n0 = bx*64, m0 = by*64. block = 128 thr = 4 warps (2m x 2n), warp tile 32x32.
__device__ __forceinline__ void split_f4(float4 v, uint2& hi, uint2& lo) {
    __nv_bfloat16 h0 = __float2bfloat16(v.x), h1 = __float2bfloat16(v.y);
    __nv_bfloat16 h2 = __float2bfloat16(v.z), h3 = __float2bfloat16(v.w);
    __nv_bfloat16 l0 = __float2bfloat16(v.x - __bfloat162float(h0));
    __nv_bfloat16 l1 = __float2bfloat16(v.y - __bfloat162float(h1));
    __nv_bfloat16 l2 = __float2bfloat16(v.z - __bfloat162float(h2));
    __nv_bfloat16 l3 = __float2bfloat16(v.w - __bfloat162float(h3));
    __nv_bfloat162 ph0(h0, h1), ph1(h2, h3), pl0(l0, l1), pl1(l2, l3);
    hi.x = *(uint32_t*)&ph0; hi.y = *(uint32_t*)&ph1;
    lo.x = *(uint32_t*)&pl0; lo.y = *(uint32_t*)&pl1;
}

__global__ void __launch_bounds__(128) k_gemm(const float* __restrict__ W1) {
    __shared__ __nv_bfloat16 Ah[64][LDM], Al[64][LDM], Bh[64][LDM], Bl[64][LDM];
    int tid = threadIdx.x;
    int warp = tid >> 5;
    int wm = warp >> 1, wn = warp & 1;
    int n0 = blockIdx.x * 64, m0 = blockIdx.y * 64;

    wmma::fragment<wmma::accumulator, 16, 16, 16, float> acc[2][2];
#pragma unroll
    for (int a = 0; a < 2; a++)
#pragma unroll
        for (int b = 0; b < 2; b++) wmma::fill_fragment(acc[a][b], 0.0f);

    int r = tid >> 1, p = tid & 1;   // 64 rows x 2 halves
    for (int kc = 0; kc < HH / 64; kc++) {
        int k0 = kc * 64;
        __syncthreads();             // previous chunk's reads done before overwrite
        const float4* ga = (const float4*)&g_phi[m0 + r][k0] + p * 8;
        const float4* gb = (const float4*)&W1[(size_t)(n0 + r) * HH + k0] + p * 8;
#pragma unroll
        for (int j = 0; j < 8; j++) {
            uint2 hi, lo;
            split_f4(ga[j], hi, lo);
            int col = p * 32 + j * 4;
            *(uint2*)&Ah[r][col] = hi;
            *(uint2*)&Al[r][col] = lo;
            split_f4(gb[j], hi, lo);
            *(uint2*)&Bh[r][col] = hi;
            *(uint2*)&Bl[r][col] = lo;
        }
        __syncthreads();
#pragma unroll
        for (int ks = 0; ks < 4; ks++) {
            int kk = ks * 16;
            wmma::fragment<wmma::matrix_a, 16, 16, 16, __nv_bfloat16, wmma::row_major> fah[2], fal[2];
            wmma::fragment<wmma::matrix_b, 16, 16, 16, __nv_bfloat16, wmma::col_major> fbh[2], fbl[2];
#pragma unroll
            for (int i = 0; i < 2; i++) {
                wmma::load_matrix_sync(fah[i], &Ah[wm * 32 + i * 16][kk], LDM);
                wmma::load_matrix_sync(fal[i], &Al[wm * 32 + i * 16][kk], LDM);
                wmma::load_matrix_sync(fbh[i], &Bh[wn * 32 + i * 16][kk], LDM);
                wmma::load_matrix_sync(fbl[i], &Bl[wn * 32 + i * 16][kk], LDM);
            }
#pragma unroll
            for (int a = 0; a < 2; a++)
#pragma unroll
                for (int b = 0; b < 2; b++) {
                    wmma::mma_sync(acc[a][b], fah[a], fbh[b], acc[a][b]);
                    wmma::mma_sync(acc[a][b], fah[a], fbl[b], acc[a][b]);
                    wmma::mma_sync(acc[a][b], fal[a], fbh[b], acc[a][b]);
                }
        }
    }
#pragma unroll
    for (int a = 0; a < 2; a++)
#pragma unroll
        for (int b = 0; b < 2; b++)
            wmma::store_matrix_sync(&g_gi[m0 + wm * 32 + a * 16][n0 + wn * 32 + b * 16],
                                    acc[a][b], N3H, wmma::mem_row_major);
}

// ---------------- layer-1 nonlinearity + projection dot -> F table ----------------
__global__ void k_tail(const float* __restrict__ bih1, const float* __restrict__ bhh1,
                       const float* __restrict__ Wp, const float* __restrict__ bp) {
    int i = blockIdx.x;
    float acc = 0.f;
    for (int ch = threadIdx.x; ch < HH; ch += 256) {
        float gr = g_gi[i][ch]          + bih1[ch];
        float gz = g_gi[i][HH + ch]     + bih1[HH + ch];
        float gn = g_gi[i][2 * HH + ch] + bih1[2 * HH + ch];
        float r = 1.f / (1.f + expf(-(gr + bhh1[ch])));
        float z = 1.f / (1.f + expf(-(gz + bhh1[HH + ch])));
        float n = tanhf(gn + r * bhh1[2 * HH + ch]);
        acc += Wp[ch] * (1.f - z) * n;
    }
    __shared__ float sm[256];
    sm[threadIdx.x] = acc; __syncthreads();
    for (int st = 128; st > 0; st >>= 1) {
        if (threadIdx.x < st) sm[threadIdx.x] += sm[threadIdx.x + st];
        __syncthreads();
    }
    if (threadIdx.x == 0) g_Ftab[i] = sm[0] + bp[0];
}

// ---------------- sequential scan: 64 independent scalar recurrences ----------------
// Per-iter chain: fma(u) -> +MAGIC -> LOP -> addr -> LDS.128 -> 3-level combine (~57 cyc).
// Domain construction guarantees true_u in [~2.9, ~125.3]: no clamp needed.
__global__ void k_scan(float* __restrict__ out) {
    __shared__ float4 tab4[NF];
    int tid = threadIdx.x;  // 64
    for (int i = tid; i < NF; i += 64) {
        float p0 = g_Ftab[i > 0 ? i - 1 : 0];
        float p1 = g_Ftab[i];
        float p2 = g_Ftab[i < NF - 1 ? i + 1 : NF - 1];
        float p3 = g_Ftab[i < NF - 2 ? i + 2 : NF - 1];
        tab4[i] = make_float4(p0, p1, p2, p3);
    }
    float R = domain_R();
    float invd = (float)(NF - 1) / (2.f * R);
    float k1 = 0.5f * invd;
    float base = R * invd - 0.5f;         // -0.5 shift: round(u') == floor(true_u)
    __syncthreads();
    const float MAGIC = 12582912.0f;      // 2^23 + 2^22
    float* o = out + tid * TT;
    float f = 0.f;
    float buf[8];
#pragma unroll
    for (int i = 0; i < 8; i++) buf[i] = g_pxT[i][tid];
    for (int t0 = 0; t0 < TT; t0 += 8) {
#pragma unroll
        for (int i = 0; i < 8; i++) {
            float pxv = buf[i];
            int tn = t0 + 8 + i;
            if (tn < TT) buf[i] = g_pxT[tn][tid];      // prefetch: off the f-chain
            float pb = fmaf(pxv, k1, base);            // independent of f
            float u = fmaf(f, k1, pb);                 // = true_u - 0.5
            float fm = u + MAGIC;
            int idx = __float_as_int(fm) & 0x7F;       // = floor(true_u), in [1,126]
            float idxf = fm - MAGIC;
            float y = u - idxf;                        // in [-0.5, 0.5)
            float4 P = tab4[idx];                      // {F[idx-1..idx+2]}
            // 4-pt Lagrange cubic; nodes at y = -1.5,-0.5,0.5,1.5
            float xx  = y + 0.5f;
            float xm1 = y - 0.5f;
            float xm2 = y - 1.5f;
            float xp1 = y + 1.5f;
            float w0 = -xx  * xm1 * xm2 * (1.f / 6.f);
            float w1 =  xp1 * xm1 * xm2 * 0.5f;
            float w2 = -xp1 * xx  * xm2 * 0.5f;
            float w3 =  xp1 * xx  * xm1 * (1.f / 6.f);
            float t0f = w0 * P.x, t1f = w1 * P.y, t2f = w2 * P.z, t3f = w3 * P.w;
            f = (t0f + t1f) + (t2f + t3f);
            o[t0 + i] = f;
        }
    }
}

extern "C" void kernel_launch(void* const* d_in, const int* in_sizes, int n_in,
                              void* d_out, int out_size) {
    const float* x     = (const float*)d_in[0];
    // d_in[1] timestamp: unused
    const float* gamma = (const float*)d_in[2];
    const float* beta  = (const float*)d_in[3];
    const float* Wih0  = (const float*)d_in[4];
    const float* bih0  = (const float*)d_in[5];
    // d_in[6] W_hh0 unused (h_prev = 0)
    const float* bhh0  = (const float*)d_in[7];
    const float* Wih1  = (const float*)d_in[8];
    const float* bih1  = (const float*)d_in[9];
    // d_in[10] W_hh1 unused
    const float* bhh1  = (const float*)d_in[11];
    const float* Wp    = (const float*)d_in[12];
    const float* bp    = (const float*)d_in[13];
    float* out = (float*)d_out;

    k_stats<<<dim3(4, 64), 256>>>(x);
    k_finalize<<<1, 1024>>>(gamma, beta, Wp, bp);
    k_px<<<BT / 8, 256>>>(x);
    k_phi<<<dim3(NF, 4), 256>>>(Wih0, bih0, bhh0);
    k_gemm<<<dim3(48, 2), 128>>>(Wih1);
    k_tail<<<NF, 256>>>(bih1, bhh1, Wp, bp);
    k_scan<<<1, 64>>>(out);
}

// round 7
// speedup vs baseline: 1.0605x; 1.0605x over previous
#include <cuda_runtime.h>
#include <math.h>
#include <cstdint>

#define BB 64
#define TT 512
#define HH 1024
#define BT (BB*TT)
#define NF 128
#define N3H (3*HH)
#define GRID 148
#define NTHR 256
#define RPB ((BT + GRID - 1) / GRID)   // 222 rows per block

// ---------------- device scratch (no allocations allowed) ----------------
__device__ float g_part_sum[GRID][HH];
__device__ float g_part_sq[GRID][HH];
__device__ float g_a[HH];
__device__ float g_red[8];        // [0..3]: C partials, [4..7]: sum|Wp| partials
__device__ unsigned g_pxmax_u;
__device__ float g_pxT[TT][BB];   // px transposed [t][b]
__device__ float g_phi[NF][HH];
__device__ float g_gi[NF][N3H];
__device__ float g_Ftab[NF];

// ---------------- grid-wide barrier (all 148 CTAs co-resident) ----------------
__device__ unsigned g_bar_count = 0;
__device__ volatile unsigned g_bar_gen = 0;

__device__ __forceinline__ void grid_sync() {
    __syncthreads();
    if (threadIdx.x == 0) {
        __threadfence();                       // publish this block's writes
        unsigned gen = g_bar_gen;
        if (atomicAdd(&g_bar_count, 1u) == GRID - 1) {
            g_bar_count = 0;
            __threadfence();                   // reset visible before release
            g_bar_gen = gen + 1;
        } else {
            while (g_bar_gen == gen) { }
        }
        __threadfence();                       // acquire
    }
    __syncthreads();
}

// R computed bit-identically wherever needed (fixed summation order, L2 loads)
__device__ __forceinline__ float load_R(float bp0) {
    float wl = ((__ldcg(&g_red[4]) + __ldcg(&g_red[5])) +
                (__ldcg(&g_red[6]) + __ldcg(&g_red[7]))) + fabsf(bp0);
    float pxmax = __uint_as_float(__ldcg((const unsigned*)&g_pxmax_u));
    return 0.5f * (pxmax + wl) * 1.02f + 0.25f;
}

__global__ void __launch_bounds__(NTHR) k_fused(
    const float* __restrict__ x,
    const float* __restrict__ gamma, const float* __restrict__ beta,
    const float* __restrict__ W0, const float* __restrict__ bih0,
    const float* __restrict__ bhh0,
    const float* __restrict__ W1, const float* __restrict__ bih1,
    const float* __restrict__ bhh1,
    const float* __restrict__ Wp, const float* __restrict__ bp,
    float* __restrict__ out)
{
    __shared__ __align__(16) float s_buf[2176];   // union: gemm tiles / reductions / scan table
    int b = blockIdx.x, tid = threadIdx.x;

    // ======== phase 1: BN partial sums (all blocks, disjoint row ranges) ========
    {
        int r0 = b * RPB, r1 = r0 + RPB; if (r1 > BT) r1 = BT;
        float s0=0.f,s1=0.f,s2=0.f,s3=0.f,q0=0.f,q1=0.f,q2=0.f,q3=0.f;
        const float* p = x + (size_t)r0 * HH + tid;
        for (int r = r0; r < r1; r++, p += HH) {
            float v0 = p[0], v1 = p[256], v2 = p[512], v3 = p[768];
            s0 += v0; q0 += v0*v0; s1 += v1; q1 += v1*v1;
            s2 += v2; q2 += v2*v2; s3 += v3; q3 += v3*v3;
        }
        g_part_sum[b][tid]     = s0; g_part_sq[b][tid]     = q0;
        g_part_sum[b][tid+256] = s1; g_part_sq[b][tid+256] = q1;
        g_part_sum[b][tid+512] = s2; g_part_sq[b][tid+512] = q2;
        g_part_sum[b][tid+768] = s3; g_part_sq[b][tid+768] = q3;
        if (b == 0 && tid == 0) g_pxmax_u = 0u;   // per-replay reset
    }
    grid_sync();

    // ======== phase 2: finalize -> a[], partial C / |Wp| sums (blocks 0..3) ========
    if (b < 4) {
        int j = b * 256 + tid;
        float s = 0.f, q = 0.f;
#pragma unroll 4
        for (int c = 0; c < GRID; c++) { s += g_part_sum[c][j]; q += g_part_sq[c][j]; }
        float mean = s * (1.0f / BT);
        float var  = q * (1.0f / BT) - mean * mean;
        float rstd = rsqrtf(var + 1e-5f);
        float gj = gamma[j], wj = Wp[j];
        g_a[j] = gj * rstd * wj;
        float cj = (beta[j] - mean * rstd * gj) * wj;
        s_buf[tid] = cj; s_buf[256 + tid] = fabsf(wj);
        __syncthreads();
        for (int st = 128; st > 0; st >>= 1) {
            if (tid < st) { s_buf[tid] += s_buf[tid + st];
                            s_buf[256 + tid] += s_buf[256 + tid + st]; }
            __syncthreads();
        }
        if (tid == 0) { g_red[b] = s_buf[0]; g_red[4 + b] = s_buf[256]; }
    }
    grid_sync();

    // ======== phase 3: px -> transposed store + global max|px| ========
    {
        float C = ((__ldcg(&g_red[0]) + __ldcg(&g_red[1])) +
                   (__ldcg(&g_red[2]) + __ldcg(&g_red[3]))) + bp[0];
        int w = tid >> 5, lane = tid & 31;
        int r0 = b * RPB, r1 = r0 + RPB; if (r1 > BT) r1 = BT;
        const float4* a4 = (const float4*)g_a;
        float4 areg[8];
#pragma unroll
        for (int i = 0; i < 8; i++) areg[i] = __ldg(&a4[lane + i * 32]);
        float mymax = 0.f;
        for (int r = r0 + w; r < r1; r += 8) {
            const float4* xr = (const float4*)(x + (size_t)r * HH);
            float acc = 0.f;
#pragma unroll
            for (int i = 0; i < 8; i++) {
                float4 xv = xr[lane + i * 32];
                acc += xv.x*areg[i].x + xv.y*areg[i].y + xv.z*areg[i].z + xv.w*areg[i].w;
            }
#pragma unroll
            for (int o = 16; o; o >>= 1) acc += __shfl_down_sync(0xFFFFFFFFu, acc, o);
            if (lane == 0) {
                float v = acc + C;
                g_pxT[r & (TT - 1)][r >> 9] = v;
                mymax = fmaxf(mymax, fabsf(v));
            }
        }
        __syncthreads();
        if (lane == 0) s_buf[w] = mymax;
        __syncthreads();
        if (tid == 0) {
            float m = fmaxf(fmaxf(fmaxf(s_buf[0], s_buf[1]), fmaxf(s_buf[2], s_buf[3])),
                            fmaxf(fmaxf(s_buf[4], s_buf[5]), fmaxf(s_buf[6], s_buf[7])));
            atomicMax(&g_pxmax_u, __float_as_uint(m));   // m>=0: uint order == float order
        }
    }
    grid_sync();

    // ======== phase 4: phi table (layer-0 GRU cell, h=0) ========
    {
        float R = load_R(bp[0]);
        float s0v = -R, delta = 2.f * R / (float)(NF - 1);
        for (int idx = b * NTHR + tid; idx < NF * HH; idx += GRID * NTHR) {
            int i = idx >> 10, j = idx & (HH - 1);
            float s = s0v + (float)i * delta;
            float ar = fmaf(s, W0[j],          bih0[j]        + bhh0[j]);
            float az = fmaf(s, W0[HH + j],     bih0[HH + j]   + bhh0[HH + j]);
            float r = 1.f / (1.f + expf(-ar));
            float z = 1.f / (1.f + expf(-az));
            float an = fmaf(s, W0[2*HH + j], fmaf(r, bhh0[2*HH + j], bih0[2*HH + j]));
            g_phi[i][j] = (1.f - z) * tanhf(an);
        }
    }
    grid_sync();

    // ======== phase 5: FFMA GEMM gi[128][3072] = phi @ W1^T (blocks 0..95) ========
    if (b < 96) {
        float (*As)[68] = (float (*)[68])s_buf;
        float (*Bs)[68] = (float (*)[68])(s_buf + 1088);
        int n0 = (b % 48) * 64, m0 = (b / 48) * 64;
        int lrow = tid >> 2, lk4 = (tid & 3) * 4;
        int mt = (tid >> 4) * 4, nt = (tid & 15) * 4;
        float acc[4][4] = {};
        for (int k0 = 0; k0 < HH; k0 += 16) {
            float4 av = *(const float4*)&g_phi[m0 + lrow][k0 + lk4];
            float4 bv = *(const float4*)&W1[(size_t)(n0 + lrow) * HH + k0 + lk4];
            As[lk4 + 0][lrow] = av.x; As[lk4 + 1][lrow] = av.y;
            As[lk4 + 2][lrow] = av.z; As[lk4 + 3][lrow] = av.w;
            Bs[lk4 + 0][lrow] = bv.x; Bs[lk4 + 1][lrow] = bv.y;
            Bs[lk4 + 2][lrow] = bv.z; Bs[lk4 + 3][lrow] = bv.w;
            __syncthreads();
#pragma unroll
            for (int kk = 0; kk < 16; kk++) {
                float4 a4v = *(const float4*)&As[kk][mt];
                float4 b4v = *(const float4*)&Bs[kk][nt];
                float a_[4] = {a4v.x, a4v.y, a4v.z, a4v.w};
                float b_[4] = {b4v.x, b4v.y, b4v.z, b4v.w};
#pragma unroll
                for (int r = 0; r < 4; r++)
#pragma unroll
                    for (int c = 0; c < 4; c++)
                        acc[r][c] = fmaf(a_[r], b_[c], acc[r][c]);
            }
            __syncthreads();
        }
#pragma unroll
        for (int r = 0; r < 4; r++) {
            float4 o = make_float4(acc[r][0], acc[r][1], acc[r][2], acc[r][3]);
            *(float4*)&g_gi[m0 + mt + r][n0 + nt] = o;
        }
    }
    grid_sync();

    // ======== phase 6: layer-1 nonlinearity + projection -> F table (blocks 0..127) ========
    if (b < NF) {
        float acc = 0.f;
        for (int ch = tid; ch < HH; ch += NTHR) {
            float gr = g_gi[b][ch]          + bih1[ch];
            float gz = g_gi[b][HH + ch]     + bih1[HH + ch];
            float gn = g_gi[b][2*HH + ch]   + bih1[2*HH + ch];
            float r = 1.f / (1.f + expf(-(gr + bhh1[ch])));
            float z = 1.f / (1.f + expf(-(gz + bhh1[HH + ch])));
            float n = tanhf(gn + r * bhh1[2*HH + ch]);
            acc += Wp[ch] * (1.f - z) * n;
        }
        s_buf[tid] = acc;
        __syncthreads();
        for (int st = 128; st > 0; st >>= 1) {
            if (tid < st) s_buf[tid] += s_buf[tid + st];
            __syncthreads();
        }
        if (tid == 0) g_Ftab[b] = s_buf[0] + bp[0];
    }
    grid_sync();

    // ======== phase 7: sequential scan, 64 scalar recurrences (block 0) ========
    if (b == 0) {
        float4* tab4 = (float4*)s_buf;
        for (int i = tid; i < NF; i += NTHR) {
            float p0 = __ldcg(&g_Ftab[i > 0 ? i - 1 : 0]);
            float p1 = __ldcg(&g_Ftab[i]);
            float p2 = __ldcg(&g_Ftab[i < NF - 1 ? i + 1 : NF - 1]);
            float p3 = __ldcg(&g_Ftab[i < NF - 2 ? i + 2 : NF - 1]);
            tab4[i] = make_float4(p0, p1, p2, p3);
        }
        __syncthreads();
        if (tid < BB) {
            float R = load_R(bp[0]);
            float invd = (float)(NF - 1) / (2.f * R);
            float k1 = 0.5f * invd;
            float base = R * invd - 0.5f;        // -0.5: round(u') == floor(true_u)
            const float MAGIC = 12582912.0f;     // 2^23 + 2^22
            float* o = out + tid * TT;
            float f = 0.f;
            float buf[8];
#pragma unroll
            for (int i = 0; i < 8; i++) buf[i] = __ldcg(&g_pxT[i][tid]);
            for (int t0 = 0; t0 < TT; t0 += 8) {
#pragma unroll
                for (int i = 0; i < 8; i++) {
                    float pxv = buf[i];
                    int tn = t0 + 8 + i;
                    if (tn < TT) buf[i] = __ldcg(&g_pxT[tn][tid]);  // off the f-chain
                    float pb = fmaf(pxv, k1, base);                 // independent of f
                    float u = fmaf(f, k1, pb);                      // = true_u - 0.5
                    float fm = u + MAGIC;
                    int idx = __float_as_int(fm) & 0x7F;            // floor(true_u) in [1,126]
                    float idxf = fm - MAGIC;
                    float y = u - idxf;                             // in [-0.5, 0.5)
                    float4 P = tab4[idx];
                    // 4-pt Lagrange cubic; nodes at y = -1.5,-0.5,0.5,1.5
                    float xx  = y + 0.5f;
                    float xm1 = y - 0.5f;
                    float xm2 = y - 1.5f;
                    float xp1 = y + 1.5f;
                    float w0 = -xx  * xm1 * xm2 * (1.f / 6.f);
                    float w1 =  xp1 * xm1 * xm2 * 0.5f;
                    float w2 = -xp1 * xx  * xm2 * 0.5f;
                    float w3 =  xp1 * xx  * xm1 * (1.f / 6.f);
                    float a0 = w0 * P.x, a1 = w1 * P.y, a2 = w2 * P.z, a3 = w3 * P.w;
                    f = (a0 + a1) + (a2 + a3);
                    o[t0 + i] = f;
                }
            }
        }
    }
}

extern "C" void kernel_launch(void* const* d_in, const int* in_sizes, int n_in,
                              void* d_out, int out_size) {
    const float* x     = (const float*)d_in[0];
    // d_in[1] timestamp: unused
    const float* gamma = (const float*)d_in[2];
    const float* beta  = (const float*)d_in[3];
    const float* Wih0  = (const float*)d_in[4];
    const float* bih0  = (const float*)d_in[5];
    // d_in[6] W_hh0 unused (h_prev = 0)
    const float* bhh0  = (const float*)d_in[7];
    const float* Wih1  = (const float*)d_in[8];
    const float* bih1  = (const float*)d_in[9];
    // d_in[10] W_hh1 unused
    const float* bhh1  = (const float*)d_in[11];
    const float* Wp    = (const float*)d_in[12];
    const float* bp    = (const float*)d_in[13];
    float* out = (float*)d_out;

    k_fused<<<GRID, NTHR>>>(x, gamma, beta, Wih0, bih0, bhh0,
                            Wih1, bih1, bhh1, Wp, bp, out);
}